// round 5
// baseline (speedup 1.0000x reference)
#include <cuda_runtime.h>
#include <cuda_fp16.h>
#include <math.h>
#include <stdint.h>

#define NROI 512
#define NPOS 128
#define NCLS 81
#define KDIM 12544   // 256*49
#define HID  1024
#define NHEADP 512   // 81 + 324 padded to 128-multiple

// ---------------- scratch (device globals; no allocs allowed) ----------------
__device__ __align__(256) __half g_featT[17408000];      // (H,W,C) fp16 FPN maps
__device__ __align__(256) __half g_x[NROI * KDIM];       // pooled, [n][bin*256+c]
__device__ __align__(256) __half g_W1T[HID * KDIM];      // K-major, permuted rows
__device__ __align__(256) __half g_W2T[HID * HID];
__device__ __align__(256) __half g_WhT[NHEADP * HID];
__device__ float g_bh[NHEADP];
__device__ __align__(256) __half g_h1[NROI * HID];
__device__ __align__(256) __half g_h2[NROI * HID];
__device__ float g_head[NROI * NHEADP];
__device__ float g_part[8 * NROI * HID];                 // split-K partials

// ---------------- helpers ----------------
__device__ __forceinline__ uint32_t smem_u32(const void* p) {
    uint32_t a;
    asm("{ .reg .u64 t; cvta.to.shared.u64 t, %1; cvt.u32.u64 %0, t; }" : "=r"(a) : "l"(p));
    return a;
}
#define CP_ASYNC16(dst, src) asm volatile("cp.async.cg.shared.global [%0], [%1], 16;" :: "r"(dst), "l"(src))
#define CP_COMMIT() asm volatile("cp.async.commit_group;" ::: "memory")
#define CP_WAIT(n)  asm volatile("cp.async.wait_group %0;" :: "n"(n) : "memory")

#define LDSM_X4(r0, r1, r2, r3, a) \
    asm volatile("ldmatrix.sync.aligned.m8n8.x4.shared.b16 {%0,%1,%2,%3}, [%4];" \
        : "=r"(r0), "=r"(r1), "=r"(r2), "=r"(r3) : "r"(a))

#define MMA16816(d, a, b0, b1) \
    asm volatile("mma.sync.aligned.m16n8k16.row.col.f32.f16.f16.f32 " \
        "{%0,%1,%2,%3}, {%4,%5,%6,%7}, {%8,%9}, {%0,%1,%2,%3};" \
        : "+f"((d)[0]), "+f"((d)[1]), "+f"((d)[2]), "+f"((d)[3]) \
        : "r"((a)[0]), "r"((a)[1]), "r"((a)[2]), "r"((a)[3]), "r"(b0), "r"(b1))

// ---------------- merged transpose (C,H,W) -> (H,W,C) fp16, all 4 levels ----------------
__global__ void transpose_all_kernel(const float* __restrict__ P2, const float* __restrict__ P3,
                                     const float* __restrict__ P4, const float* __restrict__ P5,
                                     __half* __restrict__ featT) {
    __shared__ float s[32][33];
    int b = blockIdx.x;
    int lv, lb;
    if (b < 12800)      { lv = 0; lb = b; }
    else if (b < 16000) { lv = 1; lb = b - 12800; }
    else if (b < 16800) { lv = 2; lb = b - 16000; }
    else                { lv = 3; lb = b - 16800; }
    const int Hs[4] = {200, 100, 50, 25};
    const int Ws[4] = {256, 128, 64, 32};
    const int bases[4] = {0, 13107200, 16384000, 17203200};
    const float* srcs[4] = {P2, P3, P4, P5};
    int H = Hs[lv], W = Ws[lv];
    int bxw = W >> 5;
    int bx = lb % bxw;
    int tmp = lb / bxw;
    int y  = tmp % H;
    int cz = tmp / H;

    const float* src = srcs[lv];
    __half* dst = featT + bases[lv];

    int x = bx * 32 + threadIdx.x;
    int c = cz * 32 + threadIdx.y;
    s[threadIdx.y][threadIdx.x] = src[(c * H + y) * W + x];
    __syncthreads();
    int c2 = cz * 32 + threadIdx.x;
    int x2 = bx * 32 + threadIdx.y;
    dst[(size_t)(y * W + x2) * 256 + c2] = __float2half(s[threadIdx.x][threadIdx.y]);
}

// ---------------- weight prep ----------------
__global__ void w1t_kernel(const float* __restrict__ W1, __half* __restrict__ W1T) {
    __shared__ float s[32][33];
    int kp0 = blockIdx.x * 32;
    int j0  = blockIdx.y * 32;
    int kk = kp0 + threadIdx.y;
    int r = (kk & 255) * 49 + (kk >> 8);
    s[threadIdx.y][threadIdx.x] = W1[(size_t)r * HID + j0 + threadIdx.x];
    __syncthreads();
    W1T[(size_t)(j0 + threadIdx.y) * KDIM + kp0 + threadIdx.x] =
        __float2half(s[threadIdx.x][threadIdx.y]);
}

__global__ void w2t_kernel(const float* __restrict__ W2, __half* __restrict__ W2T) {
    __shared__ float s[32][33];
    int k0 = blockIdx.x * 32;
    int j0 = blockIdx.y * 32;
    s[threadIdx.y][threadIdx.x] = W2[(size_t)(k0 + threadIdx.y) * HID + j0 + threadIdx.x];
    __syncthreads();
    W2T[(size_t)(j0 + threadIdx.y) * HID + k0 + threadIdx.x] =
        __float2half(s[threadIdx.x][threadIdx.y]);
}

__global__ void whead_kernel(const float* __restrict__ Wcls, const float* __restrict__ Wloc,
                             const float* __restrict__ bcls, const float* __restrict__ bloc,
                             __half* __restrict__ WhT, float* __restrict__ bh) {
    int j = blockIdx.y;
    int k = blockIdx.x * 256 + threadIdx.x;
    float v = 0.0f;
    if (j < NCLS) v = Wcls[(size_t)k * NCLS + j];
    else if (j < NCLS * 5) v = Wloc[(size_t)k * (NCLS * 4) + (j - NCLS)];
    WhT[(size_t)j * HID + k] = __float2half(v);
    if (blockIdx.x == 0 && threadIdx.x == 0) {
        float bv = 0.0f;
        if (j < NCLS) bv = bcls[j];
        else if (j < NCLS * 5) bv = bloc[j - NCLS];
        bh[j] = bv;
    }
}

// ---------------- RoIAlign ----------------
__global__ void pool_kernel(const float* __restrict__ rois,
                            const __half* __restrict__ featT,
                            __half* __restrict__ xout) {
    int n = blockIdx.y, bin = blockIdx.x, c = threadIdx.x;
    int oy = bin / 7, ox = bin % 7;

    float rx1 = rois[n * 4 + 0], ry1 = rois[n * 4 + 1];
    float rx2 = rois[n * 4 + 2], ry2 = rois[n * 4 + 3];
    float area = (rx2 - rx1 + 1.0f) * (ry2 - ry1 + 1.0f);
    float lf = floorf(4.0f + log2f(sqrtf(area) / 224.0f));
    lf = fminf(fmaxf(lf, 2.0f), 5.0f);
    int lv = (int)lf - 2;

    const int   Hs[4]    = {200, 100, 50, 25};
    const int   Ws[4]    = {256, 128, 64, 32};
    const int   bases[4] = {0, 13107200, 16384000, 17203200};
    const float scl[4]   = {0.25f, 0.125f, 0.0625f, 0.03125f};

    int H = Hs[lv], W = Ws[lv];
    const __half* ft = featT + bases[lv];
    float scale = scl[lv];

    float x1 = rx1 * scale, y1 = ry1 * scale;
    float x2 = rx2 * scale, y2 = ry2 * scale;
    float bw = fmaxf(x2 - x1, 1.0f) / 7.0f;
    float bh = fmaxf(y2 - y1, 1.0f) / 7.0f;

    float acc = 0.0f;
    #pragma unroll
    for (int sy = 0; sy < 2; sy++) {
        #pragma unroll
        for (int sx = 0; sx < 2; sx++) {
            float px = x1 + ((float)ox + ((float)sx + 0.5f) * 0.5f) * bw;
            float py = y1 + ((float)oy + ((float)sy + 0.5f) * 0.5f) * bh;
            bool valid = (px > -1.0f) && (px < (float)W) && (py > -1.0f) && (py < (float)H);
            if (!valid) continue;
            float xx = fminf(fmaxf(px, 0.0f), (float)(W - 1));
            float yy = fminf(fmaxf(py, 0.0f), (float)(H - 1));
            float x0f = floorf(xx), y0f = floorf(yy);
            float lx = xx - x0f, ly = yy - y0f;
            int x0 = (int)x0f, y0 = (int)y0f;
            int x1i = min(x0 + 1, W - 1), y1i = min(y0 + 1, H - 1);
            const __half* r0 = ft + (size_t)(y0  * W) * 256;
            const __half* r1 = ft + (size_t)(y1i * W) * 256;
            float w00 = (1.0f - ly) * (1.0f - lx);
            float w01 = (1.0f - ly) * lx;
            float w10 = ly * (1.0f - lx);
            float w11 = ly * lx;
            acc += w00 * __half2float(r0[x0 * 256 + c]) + w01 * __half2float(r0[x1i * 256 + c])
                 + w10 * __half2float(r1[x0 * 256 + c]) + w11 * __half2float(r1[x1i * 256 + c]);
        }
    }
    xout[(size_t)n * KDIM + bin * 256 + c] = __float2half(acc * 0.25f);
}

// ---------------- HMMA GEMM: part[z][M][N] = A[M, z-slice of K] @ Bt[N, K]^T ----------------
// BM=128, BN=128, BK=32. 512 threads = 16 warps (4 m x 4 n), warp tile 32x32.
// Buffer stride: 128 rows * 32 halves = 4096 halves = 8192 bytes.
__global__ void __launch_bounds__(512) gemm_hmma(const __half* __restrict__ A,
                                                 const __half* __restrict__ Bt,
                                                 float* __restrict__ part,
                                                 int N, int Krow, int ksplit) {
    __shared__ __align__(128) __half As[2][128 * 32];
    __shared__ __align__(128) __half Bs[2][128 * 32];

    int tid = threadIdx.x, wid = tid >> 5, lane = tid & 31;
    int m0 = blockIdx.y * 128, n0 = blockIdx.x * 128;
    int z = blockIdx.z;
    int kb0 = z * ksplit;
    int wm = (wid & 3) * 32;
    int wn = (wid >> 2) * 32;

    uint32_t sA = smem_u32(As), sB = smem_u32(Bs);
    int nch = ksplit >> 5;

    int ldr = tid >> 2, ldc = tid & 3;      // 512 threads: 128 rows x 4 chunks
    int ldsw = (ldc ^ ((ldr >> 1) & 3));
    uint32_t stA = sA + (ldr * 32 + ldsw * 8) * 2;
    uint32_t stB = sB + (ldr * 32 + ldsw * 8) * 2;
    const char* gA = (const char*)(A + (size_t)(m0 + ldr) * Krow + kb0) + ldc * 16;
    const char* gB = (const char*)(Bt + (size_t)(n0 + ldr) * Krow + kb0) + ldc * 16;

    // prefetch chunk 0
    CP_ASYNC16(stA, gA);
    CP_ASYNC16(stB, gB);
    CP_COMMIT();

    float acc[2][4][4];
    #pragma unroll
    for (int mi = 0; mi < 2; mi++)
        #pragma unroll
        for (int ni = 0; ni < 4; ni++)
            #pragma unroll
            for (int j = 0; j < 4; j++) acc[mi][ni][j] = 0.0f;

    for (int k = 0; k < nch; k++) {
        int buf = k & 1;
        if (k + 1 < nch) {
            int b = 1 - buf;
            int koff = (k + 1) << 6;   // 32 halves * 2 bytes
            CP_ASYNC16(stA + b * 8192, gA + koff);   // buffer stride 8192 BYTES
            CP_ASYNC16(stB + b * 8192, gB + koff);
            CP_COMMIT();
            CP_WAIT(1);
        } else {
            CP_WAIT(0);
        }
        __syncthreads();

        // B fragments (buffer stride 4096 HALVES)
        uint32_t bf[4][4];
        #pragma unroll
        for (int ni = 0; ni < 4; ni++) {
            int row = wn + ni * 8 + (lane & 7);
            int ch = lane >> 3;
            int sw = ch ^ ((row >> 1) & 3);
            uint32_t a = sB + (buf * 4096 + row * 32 + sw * 8) * 2;
            LDSM_X4(bf[ni][0], bf[ni][1], bf[ni][2], bf[ni][3], a);
        }
        #pragma unroll
        for (int s = 0; s < 2; s++) {
            uint32_t af[2][4];
            #pragma unroll
            for (int mi = 0; mi < 2; mi++) {
                int row = wm + mi * 16 + (lane & 15);
                int ch = 2 * s + (lane >> 4);
                int sw = ch ^ ((row >> 1) & 3);
                uint32_t a = sA + (buf * 4096 + row * 32 + sw * 8) * 2;
                LDSM_X4(af[mi][0], af[mi][1], af[mi][2], af[mi][3], a);
            }
            #pragma unroll
            for (int mi = 0; mi < 2; mi++)
                #pragma unroll
                for (int ni = 0; ni < 4; ni++)
                    MMA16816(acc[mi][ni], af[mi], bf[ni][2 * s], bf[ni][2 * s + 1]);
        }
        __syncthreads();
    }

    float* out = part + (size_t)z * NROI * N;
    #pragma unroll
    for (int mi = 0; mi < 2; mi++) {
        #pragma unroll
        for (int ni = 0; ni < 4; ni++) {
            int m = m0 + wm + mi * 16 + (lane >> 2);
            int n = n0 + wn + ni * 8 + (lane & 3) * 2;
            out[(size_t)m * N + n]           = acc[mi][ni][0];
            out[(size_t)m * N + n + 1]       = acc[mi][ni][1];
            out[(size_t)(m + 8) * N + n]     = acc[mi][ni][2];
            out[(size_t)(m + 8) * N + n + 1] = acc[mi][ni][3];
        }
    }
}

// ---------------- combine: out = act(sum_z part + bias) ----------------
template <int SPLIT, bool RELU, bool HOUT>
__global__ void combine_kernel(const float* __restrict__ part, const float* __restrict__ bias,
                               void* __restrict__ out, int N) {
    int idx = blockIdx.x * 256 + threadIdx.x;
    int MN = NROI * N;
    if (idx >= MN) return;
    int n = idx % N;
    float v = bias[n];
    #pragma unroll
    for (int z = 0; z < SPLIT; z++) v += part[(size_t)z * MN + idx];
    if (RELU) v = fmaxf(v, 0.0f);
    if (HOUT) ((__half*)out)[idx] = __float2half(v);
    else      ((float*)out)[idx] = v;
}

// ---------------- loss ----------------
__global__ void loss_kernel(const float* __restrict__ head,
                            const int* __restrict__ label, const float* __restrict__ loc,
                            float* __restrict__ out) {
    __shared__ float red[512];
    int n = threadIdx.x;
    const float* lg = head + (size_t)n * NHEADP;

    float mx = -1e30f;
    for (int j = 0; j < NCLS; j++) mx = fmaxf(mx, lg[j]);
    float s = 0.0f;
    for (int j = 0; j < NCLS; j++) s += expf(lg[j] - mx);
    int lab = label[n];
    float logp = lg[lab] - mx - logf(s);
    float contrib = -logp * (1.0f / (float)NROI);

    if (n < NPOS) {
        #pragma unroll
        for (int j = 0; j < 4; j++) {
            float d = fabsf(head[(size_t)n * NHEADP + NCLS + lab * 4 + j] - loc[n * 4 + j]);
            float sl1 = (d < 1.0f) ? 0.5f * d * d : d - 0.5f;
            contrib += sl1 * (1.0f / (float)NROI);
        }
    }
    red[n] = contrib;
    __syncthreads();
    for (int stride = 256; stride > 0; stride >>= 1) {
        if (n < stride) red[n] += red[n + stride];
        __syncthreads();
    }
    if (n == 0) out[0] = red[0];
}

// ---------------- launch ----------------
extern "C" void kernel_launch(void* const* d_in, const int* in_sizes, int n_in,
                              void* d_out, int out_size) {
    const float* P2    = (const float*)d_in[0];
    const float* P3    = (const float*)d_in[1];
    const float* P4    = (const float*)d_in[2];
    const float* P5    = (const float*)d_in[3];
    const float* rois  = (const float*)d_in[4];
    const int*   label = (const int*)  d_in[5];
    const float* loc   = (const float*)d_in[6];
    const float* W1    = (const float*)d_in[7];
    const float* b1    = (const float*)d_in[8];
    const float* W2    = (const float*)d_in[9];
    const float* b2    = (const float*)d_in[10];
    const float* Wcls  = (const float*)d_in[11];
    const float* bcls  = (const float*)d_in[12];
    const float* Wloc  = (const float*)d_in[13];
    const float* bloc  = (const float*)d_in[14];
    float* out = (float*)d_out;

    __half *featT, *xb, *w1t, *w2t, *wht, *h1, *h2;
    float *bh, *head, *partb;
    cudaGetSymbolAddress((void**)&featT, g_featT);
    cudaGetSymbolAddress((void**)&xb,    g_x);
    cudaGetSymbolAddress((void**)&w1t,   g_W1T);
    cudaGetSymbolAddress((void**)&w2t,   g_W2T);
    cudaGetSymbolAddress((void**)&wht,   g_WhT);
    cudaGetSymbolAddress((void**)&bh,    g_bh);
    cudaGetSymbolAddress((void**)&h1,    g_h1);
    cudaGetSymbolAddress((void**)&h2,    g_h2);
    cudaGetSymbolAddress((void**)&head,  g_head);
    cudaGetSymbolAddress((void**)&partb, g_part);

    // weight prep
    w1t_kernel<<<dim3(KDIM / 32, HID / 32), dim3(32, 32)>>>(W1, w1t);
    w2t_kernel<<<dim3(HID / 32, HID / 32), dim3(32, 32)>>>(W2, w2t);
    whead_kernel<<<dim3(HID / 256, NHEADP), 256>>>(Wcls, Wloc, bcls, bloc, wht, bh);

    // feature transpose to fp16 (all levels, one launch)
    transpose_all_kernel<<<17000, dim3(32, 32)>>>(P2, P3, P4, P5, featT);

    pool_kernel<<<dim3(49, NROI), 256>>>(rois, featT, xb);

    // FC1 (split-K = 8): relu(x @ W1 + b1) -> h1 fp16
    gemm_hmma<<<dim3(HID / 128, NROI / 128, 8), 512>>>(xb, w1t, partb, HID, KDIM, KDIM / 8);
    combine_kernel<8, true, true><<<(NROI * HID + 255) / 256, 256>>>(partb, b1, h1, HID);

    // FC2 (split-K = 4): relu(h1 @ W2 + b2) -> h2 fp16
    gemm_hmma<<<dim3(HID / 128, NROI / 128, 4), 512>>>(h1, w2t, partb, HID, HID, HID / 4);
    combine_kernel<4, true, true><<<(NROI * HID + 255) / 256, 256>>>(partb, b2, h2, HID);

    // heads (split-K = 4): h2 @ [Wcls|Wloc] -> fp32 [512][512]
    gemm_hmma<<<dim3(NHEADP / 128, NROI / 128, 4), 512>>>(h2, wht, partb, NHEADP, HID, HID / 4);
    combine_kernel<4, false, false><<<(NROI * NHEADP + 255) / 256, 256>>>(partb, bh, head, NHEADP);

    loss_kernel<<<1, 512>>>(head, label, loc, out);
}

// round 6
// speedup vs baseline: 1.3897x; 1.3897x over previous
#include <cuda_runtime.h>
#include <cuda_fp16.h>
#include <math.h>
#include <stdint.h>

#define NROI 512
#define NPOS 128
#define NCLS 81
#define KDIM 12544   // 256*49
#define HID  1024
#define NHEADP 512   // 81 + 324 padded

// ---------------- scratch ----------------
__device__ __align__(256) __half g_featT[17408000];      // (H,W,C) fp16 FPN maps
__device__ __align__(256) __half g_x[NROI * KDIM];       // pooled, [n][bin*256+c]
__device__ __align__(256) __half g_W1T[HID * KDIM];      // K-major, permuted
__device__ __align__(256) __half g_W2T[HID * HID];
__device__ __align__(256) __half g_WhT[NHEADP * HID];
__device__ float g_bh[NHEADP];
__device__ __align__(256) __half g_h1[NROI * HID];
__device__ __align__(256) __half g_h2[NROI * HID];
__device__ float g_head[NROI * NHEADP];
__device__ float g_part[8 * NROI * HID];

// ---------------- helpers ----------------
__device__ __forceinline__ uint32_t smem_u32(const void* p) {
    uint32_t a;
    asm("{ .reg .u64 t; cvta.to.shared.u64 t, %1; cvt.u32.u64 %0, t; }" : "=r"(a) : "l"(p));
    return a;
}
#define CP_ASYNC16(dst, src) asm volatile("cp.async.cg.shared.global [%0], [%1], 16;" :: "r"(dst), "l"(src))
#define CP_COMMIT() asm volatile("cp.async.commit_group;" ::: "memory")
#define CP_WAIT(n)  asm volatile("cp.async.wait_group %0;" :: "n"(n) : "memory")

#define LDSM_X4(r0, r1, r2, r3, a) \
    asm volatile("ldmatrix.sync.aligned.m8n8.x4.shared.b16 {%0,%1,%2,%3}, [%4];" \
        : "=r"(r0), "=r"(r1), "=r"(r2), "=r"(r3) : "r"(a))

#define MMA16816(d, a, b0, b1) \
    asm volatile("mma.sync.aligned.m16n8k16.row.col.f32.f16.f16.f32 " \
        "{%0,%1,%2,%3}, {%4,%5,%6,%7}, {%8,%9}, {%0,%1,%2,%3};" \
        : "+f"((d)[0]), "+f"((d)[1]), "+f"((d)[2]), "+f"((d)[3]) \
        : "r"((a)[0]), "r"((a)[1]), "r"((a)[2]), "r"((a)[3]), "r"(b0), "r"(b1))

// ---------------- fast transpose: (C,HW) fp32 -> (HW,C) fp16 ----------------
// block (32,32): tile = 32 positions x 64 channels (as 32 half2 pairs)
// grid.x = position tiles across levels (1600+400+100+25 = 2125), grid.y = c-group (4)
__global__ void transpose_all_v2(const float* __restrict__ P2, const float* __restrict__ P3,
                                 const float* __restrict__ P4, const float* __restrict__ P5,
                                 __half* __restrict__ featT) {
    __shared__ __half2 s[32][33];
    int bx = blockIdx.x;
    int lv, pt;
    if (bx < 1600)      { lv = 0; pt = bx; }
    else if (bx < 2000) { lv = 1; pt = bx - 1600; }
    else if (bx < 2100) { lv = 2; pt = bx - 2000; }
    else                { lv = 3; pt = bx - 2100; }
    const int HWs[4]   = {51200, 12800, 3200, 800};
    const int bases[4] = {0, 13107200, 16384000, 17203200};
    const float* srcs[4] = {P2, P3, P4, P5};
    int HW = HWs[lv];
    const float* src = srcs[lv];
    __half* dst = featT + bases[lv];

    int p0 = pt * 32;
    int c0 = blockIdx.y * 64;
    int tx = threadIdx.x, ty = threadIdx.y;

    // load two channel rows (coalesced along positions), pack half2
    float a = src[(size_t)(c0 + 2 * ty)     * HW + p0 + tx];
    float b = src[(size_t)(c0 + 2 * ty + 1) * HW + p0 + tx];
    s[ty][tx] = __floats2half2_rn(a, b);
    __syncthreads();
    // write: tx = c-pair, ty = position; 4B stores, 128B/warp
    __half2* o = (__half2*)(dst + (size_t)(p0 + ty) * 256 + c0);
    o[tx] = s[tx][ty];
}

// ---------------- fast weight transposes ----------------
// W1T[j][k'] = W1[(k'&255)*49 + (k'>>8)][j], fp16. tile 32 j x 64 k'.
__global__ void w1t_v2(const float* __restrict__ W1, __half* __restrict__ W1T) {
    __shared__ __half2 s[32][33];
    int k0 = blockIdx.x * 64;
    int j0 = blockIdx.y * 32;
    int tx = threadIdx.x, ty = threadIdx.y;
    int ka = k0 + 2 * ty, kb = ka + 1;
    int ra = (ka & 255) * 49 + (ka >> 8);
    int rb = (kb & 255) * 49 + (kb >> 8);
    float a = W1[(size_t)ra * HID + j0 + tx];
    float b = W1[(size_t)rb * HID + j0 + tx];
    s[ty][tx] = __floats2half2_rn(a, b);
    __syncthreads();
    __half2* o = (__half2*)(W1T + (size_t)(j0 + ty) * KDIM + k0);
    o[tx] = s[tx][ty];
}

// W2T[j][k] = W2[k][j]
__global__ void w2t_v2(const float* __restrict__ W2, __half* __restrict__ W2T) {
    __shared__ __half2 s[32][33];
    int k0 = blockIdx.x * 64;
    int j0 = blockIdx.y * 32;
    int tx = threadIdx.x, ty = threadIdx.y;
    float a = W2[(size_t)(k0 + 2 * ty)     * HID + j0 + tx];
    float b = W2[(size_t)(k0 + 2 * ty + 1) * HID + j0 + tx];
    s[ty][tx] = __floats2half2_rn(a, b);
    __syncthreads();
    __half2* o = (__half2*)(W2T + (size_t)(j0 + ty) * HID + k0);
    o[tx] = s[tx][ty];
}

__global__ void whead_kernel(const float* __restrict__ Wcls, const float* __restrict__ Wloc,
                             const float* __restrict__ bcls, const float* __restrict__ bloc,
                             __half* __restrict__ WhT, float* __restrict__ bh) {
    int j = blockIdx.y;
    int k = blockIdx.x * 256 + threadIdx.x;
    float v = 0.0f;
    if (j < NCLS) v = Wcls[(size_t)k * NCLS + j];
    else if (j < NCLS * 5) v = Wloc[(size_t)k * (NCLS * 4) + (j - NCLS)];
    WhT[(size_t)j * HID + k] = __float2half(v);
    if (blockIdx.x == 0 && threadIdx.x == 0) {
        float bv = 0.0f;
        if (j < NCLS) bv = bcls[j];
        else if (j < NCLS * 5) bv = bloc[j - NCLS];
        bh[j] = bv;
    }
}

// ---------------- RoIAlign ----------------
__global__ void pool_kernel(const float* __restrict__ rois,
                            const __half* __restrict__ featT,
                            __half* __restrict__ xout) {
    int n = blockIdx.y, bin = blockIdx.x, c = threadIdx.x;
    int oy = bin / 7, ox = bin % 7;

    float rx1 = rois[n * 4 + 0], ry1 = rois[n * 4 + 1];
    float rx2 = rois[n * 4 + 2], ry2 = rois[n * 4 + 3];
    float area = (rx2 - rx1 + 1.0f) * (ry2 - ry1 + 1.0f);
    float lf = floorf(4.0f + log2f(sqrtf(area) / 224.0f));
    lf = fminf(fmaxf(lf, 2.0f), 5.0f);
    int lv = (int)lf - 2;

    const int   Hs[4]    = {200, 100, 50, 25};
    const int   Ws[4]    = {256, 128, 64, 32};
    const int   bases[4] = {0, 13107200, 16384000, 17203200};
    const float scl[4]   = {0.25f, 0.125f, 0.0625f, 0.03125f};

    int H = Hs[lv], W = Ws[lv];
    const __half* ft = featT + bases[lv];
    float scale = scl[lv];

    float x1 = rx1 * scale, y1 = ry1 * scale;
    float x2 = rx2 * scale, y2 = ry2 * scale;
    float bw = fmaxf(x2 - x1, 1.0f) / 7.0f;
    float bh = fmaxf(y2 - y1, 1.0f) / 7.0f;

    float acc = 0.0f;
    #pragma unroll
    for (int sy = 0; sy < 2; sy++) {
        #pragma unroll
        for (int sx = 0; sx < 2; sx++) {
            float px = x1 + ((float)ox + ((float)sx + 0.5f) * 0.5f) * bw;
            float py = y1 + ((float)oy + ((float)sy + 0.5f) * 0.5f) * bh;
            bool valid = (px > -1.0f) && (px < (float)W) && (py > -1.0f) && (py < (float)H);
            if (!valid) continue;
            float xx = fminf(fmaxf(px, 0.0f), (float)(W - 1));
            float yy = fminf(fmaxf(py, 0.0f), (float)(H - 1));
            float x0f = floorf(xx), y0f = floorf(yy);
            float lx = xx - x0f, ly = yy - y0f;
            int x0 = (int)x0f, y0 = (int)y0f;
            int x1i = min(x0 + 1, W - 1), y1i = min(y0 + 1, H - 1);
            const __half* r0 = ft + (size_t)(y0  * W) * 256;
            const __half* r1 = ft + (size_t)(y1i * W) * 256;
            float w00 = (1.0f - ly) * (1.0f - lx);
            float w01 = (1.0f - ly) * lx;
            float w10 = ly * (1.0f - lx);
            float w11 = ly * lx;
            acc += w00 * __half2float(r0[x0 * 256 + c]) + w01 * __half2float(r0[x1i * 256 + c])
                 + w10 * __half2float(r1[x0 * 256 + c]) + w11 * __half2float(r1[x1i * 256 + c]);
        }
    }
    xout[(size_t)n * KDIM + bin * 256 + c] = __float2half(acc * 0.25f);
}

// ---------------- HMMA GEMM (R3-proven): part[z][M][N] = A @ Bt^T ----------------
// BM=128, BN=64, BK=32. 256 threads = 8 warps (4 m x 2 n), warp tile 32x32.
__global__ void __launch_bounds__(256) gemm_hmma(const __half* __restrict__ A,
                                                 const __half* __restrict__ Bt,
                                                 float* __restrict__ part,
                                                 int N, int Krow, int ksplit) {
    __shared__ __align__(128) __half As[2][128 * 32];
    __shared__ __align__(128) __half Bs[2][64 * 32];

    int tid = threadIdx.x, wid = tid >> 5, lane = tid & 31;
    int m0 = blockIdx.y * 128, n0 = blockIdx.x * 64;
    int z = blockIdx.z;
    int kb0 = z * ksplit;
    int wm = (wid & 3) * 32;
    int wn = (wid >> 2) * 32;

    uint32_t sA = smem_u32(As), sB = smem_u32(Bs);
    int nch = ksplit >> 5;

    int ldr = tid >> 2, ldc = tid & 3;

    {
        #pragma unroll
        for (int i = 0; i < 2; i++) {
            int row = ldr + i * 64;
            int sw = (ldc ^ ((row >> 1) & 3));
            CP_ASYNC16(sA + (row * 32 + sw * 8) * 2,
                       (const char*)(A + (size_t)(m0 + row) * Krow + kb0) + ldc * 16);
        }
        {
            int row = ldr;
            int sw = (ldc ^ ((row >> 1) & 3));
            CP_ASYNC16(sB + (row * 32 + sw * 8) * 2,
                       (const char*)(Bt + (size_t)(n0 + row) * Krow + kb0) + ldc * 16);
        }
        CP_COMMIT();
    }

    float acc[2][4][4];
    #pragma unroll
    for (int mi = 0; mi < 2; mi++)
        #pragma unroll
        for (int ni = 0; ni < 4; ni++)
            #pragma unroll
            for (int j = 0; j < 4; j++) acc[mi][ni][j] = 0.0f;

    for (int k = 0; k < nch; k++) {
        int buf = k & 1;
        if (k + 1 < nch) {
            int b = 1 - buf;
            int kg = kb0 + ((k + 1) << 5);
            #pragma unroll
            for (int i = 0; i < 2; i++) {
                int row = ldr + i * 64;
                int sw = (ldc ^ ((row >> 1) & 3));
                CP_ASYNC16(sA + (b * 4096 + row * 32 + sw * 8) * 2,
                           (const char*)(A + (size_t)(m0 + row) * Krow + kg) + ldc * 16);
            }
            {
                int row = ldr;
                int sw = (ldc ^ ((row >> 1) & 3));
                CP_ASYNC16(sB + (b * 2048 + row * 32 + sw * 8) * 2,
                           (const char*)(Bt + (size_t)(n0 + row) * Krow + kg) + ldc * 16);
            }
            CP_COMMIT();
            CP_WAIT(1);
        } else {
            CP_WAIT(0);
        }
        __syncthreads();

        uint32_t bf[4][4];
        #pragma unroll
        for (int ni = 0; ni < 4; ni++) {
            int row = wn + ni * 8 + (lane & 7);
            int ch = lane >> 3;
            int sw = ch ^ ((row >> 1) & 3);
            uint32_t a = sB + (buf * 2048 + row * 32 + sw * 8) * 2;
            LDSM_X4(bf[ni][0], bf[ni][1], bf[ni][2], bf[ni][3], a);
        }
        #pragma unroll
        for (int s = 0; s < 2; s++) {
            uint32_t af[2][4];
            #pragma unroll
            for (int mi = 0; mi < 2; mi++) {
                int row = wm + mi * 16 + (lane & 15);
                int ch = 2 * s + (lane >> 4);
                int sw = ch ^ ((row >> 1) & 3);
                uint32_t a = sA + (buf * 4096 + row * 32 + sw * 8) * 2;
                LDSM_X4(af[mi][0], af[mi][1], af[mi][2], af[mi][3], a);
            }
            #pragma unroll
            for (int mi = 0; mi < 2; mi++)
                #pragma unroll
                for (int ni = 0; ni < 4; ni++)
                    MMA16816(acc[mi][ni], af[mi], bf[ni][2 * s], bf[ni][2 * s + 1]);
        }
        __syncthreads();
    }

    float* out = part + (size_t)z * NROI * N;
    #pragma unroll
    for (int mi = 0; mi < 2; mi++) {
        #pragma unroll
        for (int ni = 0; ni < 4; ni++) {
            int m = m0 + wm + mi * 16 + (lane >> 2);
            int n = n0 + wn + ni * 8 + (lane & 3) * 2;
            out[(size_t)m * N + n]           = acc[mi][ni][0];
            out[(size_t)m * N + n + 1]       = acc[mi][ni][1];
            out[(size_t)(m + 8) * N + n]     = acc[mi][ni][2];
            out[(size_t)(m + 8) * N + n + 1] = acc[mi][ni][3];
        }
    }
}

// ---------------- combine ----------------
template <int SPLIT, bool RELU, bool HOUT>
__global__ void combine_kernel(const float* __restrict__ part, const float* __restrict__ bias,
                               void* __restrict__ out, int N) {
    int idx = blockIdx.x * 256 + threadIdx.x;
    int MN = NROI * N;
    if (idx >= MN) return;
    int n = idx % N;
    float v = bias[n];
    #pragma unroll
    for (int z = 0; z < SPLIT; z++) v += part[(size_t)z * MN + idx];
    if (RELU) v = fmaxf(v, 0.0f);
    if (HOUT) ((__half*)out)[idx] = __float2half(v);
    else      ((float*)out)[idx] = v;
}

// ---------------- loss ----------------
__global__ void loss_kernel(const float* __restrict__ head,
                            const int* __restrict__ label, const float* __restrict__ loc,
                            float* __restrict__ out) {
    __shared__ float red[512];
    int n = threadIdx.x;
    const float* lg = head + (size_t)n * NHEADP;

    float mx = -1e30f;
    for (int j = 0; j < NCLS; j++) mx = fmaxf(mx, lg[j]);
    float s = 0.0f;
    for (int j = 0; j < NCLS; j++) s += expf(lg[j] - mx);
    int lab = label[n];
    float logp = lg[lab] - mx - logf(s);
    float contrib = -logp * (1.0f / (float)NROI);

    if (n < NPOS) {
        #pragma unroll
        for (int j = 0; j < 4; j++) {
            float d = fabsf(head[(size_t)n * NHEADP + NCLS + lab * 4 + j] - loc[n * 4 + j]);
            float sl1 = (d < 1.0f) ? 0.5f * d * d : d - 0.5f;
            contrib += sl1 * (1.0f / (float)NROI);
        }
    }
    red[n] = contrib;
    __syncthreads();
    for (int stride = 256; stride > 0; stride >>= 1) {
        if (n < stride) red[n] += red[n + stride];
        __syncthreads();
    }
    if (n == 0) out[0] = red[0];
}

// ---------------- launch ----------------
extern "C" void kernel_launch(void* const* d_in, const int* in_sizes, int n_in,
                              void* d_out, int out_size) {
    const float* P2    = (const float*)d_in[0];
    const float* P3    = (const float*)d_in[1];
    const float* P4    = (const float*)d_in[2];
    const float* P5    = (const float*)d_in[3];
    const float* rois  = (const float*)d_in[4];
    const int*   label = (const int*)  d_in[5];
    const float* loc   = (const float*)d_in[6];
    const float* W1    = (const float*)d_in[7];
    const float* b1    = (const float*)d_in[8];
    const float* W2    = (const float*)d_in[9];
    const float* b2    = (const float*)d_in[10];
    const float* Wcls  = (const float*)d_in[11];
    const float* bcls  = (const float*)d_in[12];
    const float* Wloc  = (const float*)d_in[13];
    const float* bloc  = (const float*)d_in[14];
    float* out = (float*)d_out;

    __half *featT, *xb, *w1t, *w2t, *wht, *h1, *h2;
    float *bh, *head, *partb;
    cudaGetSymbolAddress((void**)&featT, g_featT);
    cudaGetSymbolAddress((void**)&xb,    g_x);
    cudaGetSymbolAddress((void**)&w1t,   g_W1T);
    cudaGetSymbolAddress((void**)&w2t,   g_W2T);
    cudaGetSymbolAddress((void**)&wht,   g_WhT);
    cudaGetSymbolAddress((void**)&bh,    g_bh);
    cudaGetSymbolAddress((void**)&h1,    g_h1);
    cudaGetSymbolAddress((void**)&h2,    g_h2);
    cudaGetSymbolAddress((void**)&head,  g_head);
    cudaGetSymbolAddress((void**)&partb, g_part);

    // weight prep (half2 tiles)
    w1t_v2<<<dim3(KDIM / 64, HID / 32), dim3(32, 32)>>>(W1, w1t);
    w2t_v2<<<dim3(HID / 64, HID / 32), dim3(32, 32)>>>(W2, w2t);
    whead_kernel<<<dim3(HID / 256, NHEADP), 256>>>(Wcls, Wloc, bcls, bloc, wht, bh);

    // feature transpose (half2 tiles, one launch)
    transpose_all_v2<<<dim3(2125, 4), dim3(32, 32)>>>(P2, P3, P4, P5, featT);

    pool_kernel<<<dim3(49, NROI), 256>>>(rois, featT, xb);

    // FC1 (split-K = 4)
    gemm_hmma<<<dim3(HID / 64, NROI / 128, 4), 256>>>(xb, w1t, partb, HID, KDIM, KDIM / 4);
    combine_kernel<4, true, true><<<(NROI * HID + 255) / 256, 256>>>(partb, b1, h1, HID);

    // FC2 (split-K = 2)
    gemm_hmma<<<dim3(HID / 64, NROI / 128, 2), 256>>>(h1, w2t, partb, HID, HID, HID / 2);
    combine_kernel<2, true, true><<<(NROI * HID + 255) / 256, 256>>>(partb, b2, h2, HID);

    // heads (split-K = 2)
    gemm_hmma<<<dim3(NHEADP / 64, NROI / 128, 2), 256>>>(h2, wht, partb, NHEADP, HID, HID / 2);
    combine_kernel<2, false, false><<<(NROI * NHEADP + 255) / 256, 256>>>(partb, bh, head, NHEADP);

    loss_kernel<<<1, 512>>>(head, label, loc, out);
}

// round 7
// speedup vs baseline: 1.7919x; 1.2893x over previous
#include <cuda_runtime.h>
#include <cuda_fp16.h>
#include <math.h>
#include <stdint.h>

#define NROI 512
#define NPOS 128
#define NCLS 81
#define KDIM 12544   // 256*49
#define HID  1024
#define NHEADP 512

// ---------------- scratch ----------------
__device__ __align__(256) __half g_featT[17408000];
__device__ __align__(256) __half g_x[NROI * KDIM];
__device__ __align__(256) __half g_W1T[HID * KDIM];
__device__ __align__(256) __half g_W2T[HID * HID];
__device__ __align__(256) __half g_WhT[NHEADP * HID];
__device__ float g_bh[NHEADP];
__device__ __align__(256) __half g_h1[NROI * HID];
__device__ __align__(256) __half g_h2[NROI * HID];
__device__ float g_head[NROI * NHEADP];
__device__ float g_part[8 * NROI * HID];

// ---------------- helpers ----------------
__device__ __forceinline__ uint32_t smem_u32(const void* p) {
    uint32_t a;
    asm("{ .reg .u64 t; cvta.to.shared.u64 t, %1; cvt.u32.u64 %0, t; }" : "=r"(a) : "l"(p));
    return a;
}
#define CP_ASYNC16(dst, src) asm volatile("cp.async.cg.shared.global [%0], [%1], 16;" :: "r"(dst), "l"(src))
#define CP_COMMIT() asm volatile("cp.async.commit_group;" ::: "memory")
#define CP_WAIT(n)  asm volatile("cp.async.wait_group %0;" :: "n"(n) : "memory")

#define LDSM_X4(r0, r1, r2, r3, a) \
    asm volatile("ldmatrix.sync.aligned.m8n8.x4.shared.b16 {%0,%1,%2,%3}, [%4];" \
        : "=r"(r0), "=r"(r1), "=r"(r2), "=r"(r3) : "r"(a))

#define MMA16816(d, a, b0, b1) \
    asm volatile("mma.sync.aligned.m16n8k16.row.col.f32.f16.f16.f32 " \
        "{%0,%1,%2,%3}, {%4,%5,%6,%7}, {%8,%9}, {%0,%1,%2,%3};" \
        : "+f"((d)[0]), "+f"((d)[1]), "+f"((d)[2]), "+f"((d)[3]) \
        : "r"((a)[0]), "r"((a)[1]), "r"((a)[2]), "r"((a)[3]), "r"(b0), "r"(b1))

// ============ transpose v3: (C,HW) fp32 -> (HW,C) fp16, 256 thr, 16B ops ============
// tile = 32 positions x 256 channels. grid.x = 2125 position-tiles across levels.
__global__ void __launch_bounds__(256) transpose_all_v3(
        const float* __restrict__ P2, const float* __restrict__ P3,
        const float* __restrict__ P4, const float* __restrict__ P5,
        __half* __restrict__ featT) {
    __shared__ __align__(16) __half2 s2[32][132];   // 528B rows: 16B-aligned, conflict-free
    int bx = blockIdx.x;
    int lv, pt;
    if (bx < 1600)      { lv = 0; pt = bx; }
    else if (bx < 2000) { lv = 1; pt = bx - 1600; }
    else if (bx < 2100) { lv = 2; pt = bx - 2000; }
    else                { lv = 3; pt = bx - 2100; }
    const int HWs[4]   = {51200, 12800, 3200, 800};
    const int bases[4] = {0, 13107200, 16384000, 17203200};
    const float* srcs[4] = {P2, P3, P4, P5};
    int HW = HWs[lv];
    const float* src = srcs[lv];
    __half* dst = featT + bases[lv];

    int p0 = pt * 32;
    int w = threadIdx.x >> 5, l = threadIdx.x & 31;

    #pragma unroll
    for (int m = 0; m < 4; m++) {
        int cp0 = w * 16 + m * 4;
        __half2 v[4];
        #pragma unroll
        for (int q = 0; q < 4; q++) {
            int c = 2 * (cp0 + q);
            float a = src[(size_t)c * HW + p0 + l];
            float b = src[(size_t)(c + 1) * HW + p0 + l];
            v[q] = __floats2half2_rn(a, b);
        }
        *(uint4*)&s2[l][cp0] = *(uint4*)v;
    }
    __syncthreads();
    #pragma unroll
    for (int j = 0; j < 4; j++) {
        int idx = j * 256 + threadIdx.x;
        int pos = idx >> 5, seg = idx & 31;
        uint4 val = *(uint4*)&s2[pos][seg * 4];
        *(uint4*)(dst + (size_t)(p0 + pos) * 256 + seg * 8) = val;
    }
}

// ============ W1 -> W1T[j][k'] fp16, permuted: tile 32 j x 256 k' ============
__global__ void __launch_bounds__(256) w1t_v3(const float* __restrict__ W1,
                                              __half* __restrict__ W1T) {
    __shared__ __align__(16) __half2 s2[32][132];
    int k0 = blockIdx.x * 256;
    int j0 = blockIdx.y * 32;
    int w = threadIdx.x >> 5, l = threadIdx.x & 31;

    #pragma unroll
    for (int m = 0; m < 4; m++) {
        int cp0 = w * 16 + m * 4;
        __half2 v[4];
        #pragma unroll
        for (int q = 0; q < 4; q++) {
            int ka = k0 + 2 * (cp0 + q), kb = ka + 1;
            int ra = (ka & 255) * 49 + (ka >> 8);
            int rb = (kb & 255) * 49 + (kb >> 8);
            float a = W1[(size_t)ra * HID + j0 + l];
            float b = W1[(size_t)rb * HID + j0 + l];
            v[q] = __floats2half2_rn(a, b);
        }
        *(uint4*)&s2[l][cp0] = *(uint4*)v;
    }
    __syncthreads();
    #pragma unroll
    for (int j = 0; j < 4; j++) {
        int idx = j * 256 + threadIdx.x;
        int jr = idx >> 5, seg = idx & 31;
        uint4 val = *(uint4*)&s2[jr][seg * 4];
        *(uint4*)(W1T + (size_t)(j0 + jr) * KDIM + k0 + seg * 8) = val;
    }
}

// ============ W2 -> W2T[j][k] fp16: tile 32 j x 256 k ============
__global__ void __launch_bounds__(256) w2t_v3(const float* __restrict__ W2,
                                              __half* __restrict__ W2T) {
    __shared__ __align__(16) __half2 s2[32][132];
    int k0 = blockIdx.x * 256;
    int j0 = blockIdx.y * 32;
    int w = threadIdx.x >> 5, l = threadIdx.x & 31;

    #pragma unroll
    for (int m = 0; m < 4; m++) {
        int cp0 = w * 16 + m * 4;
        __half2 v[4];
        #pragma unroll
        for (int q = 0; q < 4; q++) {
            int ka = k0 + 2 * (cp0 + q);
            float a = W2[(size_t)ka * HID + j0 + l];
            float b = W2[(size_t)(ka + 1) * HID + j0 + l];
            v[q] = __floats2half2_rn(a, b);
        }
        *(uint4*)&s2[l][cp0] = *(uint4*)v;
    }
    __syncthreads();
    #pragma unroll
    for (int j = 0; j < 4; j++) {
        int idx = j * 256 + threadIdx.x;
        int jr = idx >> 5, seg = idx & 31;
        uint4 val = *(uint4*)&s2[jr][seg * 4];
        *(uint4*)(W2T + (size_t)(j0 + jr) * HID + k0 + seg * 8) = val;
    }
}

__global__ void whead_kernel(const float* __restrict__ Wcls, const float* __restrict__ Wloc,
                             const float* __restrict__ bcls, const float* __restrict__ bloc,
                             __half* __restrict__ WhT, float* __restrict__ bh) {
    int j = blockIdx.y;
    int k = blockIdx.x * 256 + threadIdx.x;
    float v = 0.0f;
    if (j < NCLS) v = Wcls[(size_t)k * NCLS + j];
    else if (j < NCLS * 5) v = Wloc[(size_t)k * (NCLS * 4) + (j - NCLS)];
    WhT[(size_t)j * HID + k] = __float2half(v);
    if (blockIdx.x == 0 && threadIdx.x == 0) {
        float bv = 0.0f;
        if (j < NCLS) bv = bcls[j];
        else if (j < NCLS * 5) bv = bloc[j - NCLS];
        bh[j] = bv;
    }
}

// ============ RoIAlign v2: one block per ROI, half2 channels ============
// 256 threads: cidx = tid&127 (channel pair), h = tid>>7 (bin parity)
__global__ void __launch_bounds__(256) pool_v2(const float* __restrict__ rois,
                                               const __half2* __restrict__ featT2,
                                               __half2* __restrict__ xout2) {
    int n = blockIdx.x;
    int cidx = threadIdx.x & 127;
    int h = threadIdx.x >> 7;

    float rx1 = rois[n * 4 + 0], ry1 = rois[n * 4 + 1];
    float rx2 = rois[n * 4 + 2], ry2 = rois[n * 4 + 3];
    float area = (rx2 - rx1 + 1.0f) * (ry2 - ry1 + 1.0f);
    float lf = floorf(4.0f + log2f(sqrtf(area) / 224.0f));
    lf = fminf(fmaxf(lf, 2.0f), 5.0f);
    int lv = (int)lf - 2;

    const int   Hs[4]     = {200, 100, 50, 25};
    const int   Ws[4]     = {256, 128, 64, 32};
    const int   bases2[4] = {0, 6553600, 8192000, 8601600};   // half2 units
    const float scl[4]    = {0.25f, 0.125f, 0.0625f, 0.03125f};

    int H = Hs[lv], W = Ws[lv];
    const __half2* ft = featT2 + bases2[lv];
    float scale = scl[lv];

    float x1 = rx1 * scale, y1 = ry1 * scale;
    float x2 = rx2 * scale, y2 = ry2 * scale;
    float bw = fmaxf(x2 - x1, 1.0f) / 7.0f;
    float bh = fmaxf(y2 - y1, 1.0f) / 7.0f;

    for (int bin = h; bin < 49; bin += 2) {
        int oy = bin / 7, ox = bin % 7;
        float2 acc = make_float2(0.0f, 0.0f);
        #pragma unroll
        for (int sy = 0; sy < 2; sy++) {
            #pragma unroll
            for (int sx = 0; sx < 2; sx++) {
                float px = x1 + ((float)ox + ((float)sx + 0.5f) * 0.5f) * bw;
                float py = y1 + ((float)oy + ((float)sy + 0.5f) * 0.5f) * bh;
                bool valid = (px > -1.0f) && (px < (float)W) && (py > -1.0f) && (py < (float)H);
                if (!valid) continue;
                float xx = fminf(fmaxf(px, 0.0f), (float)(W - 1));
                float yy = fminf(fmaxf(py, 0.0f), (float)(H - 1));
                float x0f = floorf(xx), y0f = floorf(yy);
                float lx = xx - x0f, ly = yy - y0f;
                int x0 = (int)x0f, y0 = (int)y0f;
                int x1i = min(x0 + 1, W - 1), y1i = min(y0 + 1, H - 1);
                const __half2* r0 = ft + (size_t)(y0  * W) * 128;
                const __half2* r1 = ft + (size_t)(y1i * W) * 128;
                float w00 = (1.0f - ly) * (1.0f - lx);
                float w01 = (1.0f - ly) * lx;
                float w10 = ly * (1.0f - lx);
                float w11 = ly * lx;
                float2 v00 = __half22float2(r0[x0  * 128 + cidx]);
                float2 v01 = __half22float2(r0[x1i * 128 + cidx]);
                float2 v10 = __half22float2(r1[x0  * 128 + cidx]);
                float2 v11 = __half22float2(r1[x1i * 128 + cidx]);
                acc.x += w00 * v00.x + w01 * v01.x + w10 * v10.x + w11 * v11.x;
                acc.y += w00 * v00.y + w01 * v01.y + w10 * v10.y + w11 * v11.y;
            }
        }
        xout2[(size_t)n * (KDIM / 2) + bin * 128 + cidx] =
            __floats2half2_rn(acc.x * 0.25f, acc.y * 0.25f);
    }
}

// ---------------- HMMA GEMM (proven): part[z][M][N] = A @ Bt^T ----------------
__global__ void __launch_bounds__(256) gemm_hmma(const __half* __restrict__ A,
                                                 const __half* __restrict__ Bt,
                                                 float* __restrict__ part,
                                                 int N, int Krow, int ksplit) {
    __shared__ __align__(128) __half As[2][128 * 32];
    __shared__ __align__(128) __half Bs[2][64 * 32];

    int tid = threadIdx.x, wid = tid >> 5, lane = tid & 31;
    int m0 = blockIdx.y * 128, n0 = blockIdx.x * 64;
    int z = blockIdx.z;
    int kb0 = z * ksplit;
    int wm = (wid & 3) * 32;
    int wn = (wid >> 2) * 32;

    uint32_t sA = smem_u32(As), sB = smem_u32(Bs);
    int nch = ksplit >> 5;

    int ldr = tid >> 2, ldc = tid & 3;

    {
        #pragma unroll
        for (int i = 0; i < 2; i++) {
            int row = ldr + i * 64;
            int sw = (ldc ^ ((row >> 1) & 3));
            CP_ASYNC16(sA + (row * 32 + sw * 8) * 2,
                       (const char*)(A + (size_t)(m0 + row) * Krow + kb0) + ldc * 16);
        }
        {
            int row = ldr;
            int sw = (ldc ^ ((row >> 1) & 3));
            CP_ASYNC16(sB + (row * 32 + sw * 8) * 2,
                       (const char*)(Bt + (size_t)(n0 + row) * Krow + kb0) + ldc * 16);
        }
        CP_COMMIT();
    }

    float acc[2][4][4];
    #pragma unroll
    for (int mi = 0; mi < 2; mi++)
        #pragma unroll
        for (int ni = 0; ni < 4; ni++)
            #pragma unroll
            for (int j = 0; j < 4; j++) acc[mi][ni][j] = 0.0f;

    for (int k = 0; k < nch; k++) {
        int buf = k & 1;
        if (k + 1 < nch) {
            int b = 1 - buf;
            int kg = kb0 + ((k + 1) << 5);
            #pragma unroll
            for (int i = 0; i < 2; i++) {
                int row = ldr + i * 64;
                int sw = (ldc ^ ((row >> 1) & 3));
                CP_ASYNC16(sA + (b * 4096 + row * 32 + sw * 8) * 2,
                           (const char*)(A + (size_t)(m0 + row) * Krow + kg) + ldc * 16);
            }
            {
                int row = ldr;
                int sw = (ldc ^ ((row >> 1) & 3));
                CP_ASYNC16(sB + (b * 2048 + row * 32 + sw * 8) * 2,
                           (const char*)(Bt + (size_t)(n0 + row) * Krow + kg) + ldc * 16);
            }
            CP_COMMIT();
            CP_WAIT(1);
        } else {
            CP_WAIT(0);
        }
        __syncthreads();

        uint32_t bf[4][4];
        #pragma unroll
        for (int ni = 0; ni < 4; ni++) {
            int row = wn + ni * 8 + (lane & 7);
            int ch = lane >> 3;
            int sw = ch ^ ((row >> 1) & 3);
            uint32_t a = sB + (buf * 2048 + row * 32 + sw * 8) * 2;
            LDSM_X4(bf[ni][0], bf[ni][1], bf[ni][2], bf[ni][3], a);
        }
        #pragma unroll
        for (int s = 0; s < 2; s++) {
            uint32_t af[2][4];
            #pragma unroll
            for (int mi = 0; mi < 2; mi++) {
                int row = wm + mi * 16 + (lane & 15);
                int ch = 2 * s + (lane >> 4);
                int sw = ch ^ ((row >> 1) & 3);
                uint32_t a = sA + (buf * 4096 + row * 32 + sw * 8) * 2;
                LDSM_X4(af[mi][0], af[mi][1], af[mi][2], af[mi][3], a);
            }
            #pragma unroll
            for (int mi = 0; mi < 2; mi++)
                #pragma unroll
                for (int ni = 0; ni < 4; ni++)
                    MMA16816(acc[mi][ni], af[mi], bf[ni][2 * s], bf[ni][2 * s + 1]);
        }
        __syncthreads();
    }

    float* out = part + (size_t)z * NROI * N;
    #pragma unroll
    for (int mi = 0; mi < 2; mi++) {
        #pragma unroll
        for (int ni = 0; ni < 4; ni++) {
            int m = m0 + wm + mi * 16 + (lane >> 2);
            int n = n0 + wn + ni * 8 + (lane & 3) * 2;
            out[(size_t)m * N + n]           = acc[mi][ni][0];
            out[(size_t)m * N + n + 1]       = acc[mi][ni][1];
            out[(size_t)(m + 8) * N + n]     = acc[mi][ni][2];
            out[(size_t)(m + 8) * N + n + 1] = acc[mi][ni][3];
        }
    }
}

// ---------------- combine ----------------
template <int SPLIT, bool RELU, bool HOUT>
__global__ void combine_kernel(const float* __restrict__ part, const float* __restrict__ bias,
                               void* __restrict__ out, int N) {
    int idx = blockIdx.x * 256 + threadIdx.x;
    int MN = NROI * N;
    if (idx >= MN) return;
    int n = idx % N;
    float v = bias[n];
    #pragma unroll
    for (int z = 0; z < SPLIT; z++) v += part[(size_t)z * MN + idx];
    if (RELU) v = fmaxf(v, 0.0f);
    if (HOUT) ((__half*)out)[idx] = __float2half(v);
    else      ((float*)out)[idx] = v;
}

// ---------------- loss ----------------
__global__ void loss_kernel(const float* __restrict__ head,
                            const int* __restrict__ label, const float* __restrict__ loc,
                            float* __restrict__ out) {
    __shared__ float red[512];
    int n = threadIdx.x;
    const float* lg = head + (size_t)n * NHEADP;

    float mx = -1e30f;
    for (int j = 0; j < NCLS; j++) mx = fmaxf(mx, lg[j]);
    float s = 0.0f;
    for (int j = 0; j < NCLS; j++) s += expf(lg[j] - mx);
    int lab = label[n];
    float logp = lg[lab] - mx - logf(s);
    float contrib = -logp * (1.0f / (float)NROI);

    if (n < NPOS) {
        #pragma unroll
        for (int j = 0; j < 4; j++) {
            float d = fabsf(head[(size_t)n * NHEADP + NCLS + lab * 4 + j] - loc[n * 4 + j]);
            float sl1 = (d < 1.0f) ? 0.5f * d * d : d - 0.5f;
            contrib += sl1 * (1.0f / (float)NROI);
        }
    }
    red[n] = contrib;
    __syncthreads();
    for (int stride = 256; stride > 0; stride >>= 1) {
        if (n < stride) red[n] += red[n + stride];
        __syncthreads();
    }
    if (n == 0) out[0] = red[0];
}

// ---------------- launch ----------------
extern "C" void kernel_launch(void* const* d_in, const int* in_sizes, int n_in,
                              void* d_out, int out_size) {
    const float* P2    = (const float*)d_in[0];
    const float* P3    = (const float*)d_in[1];
    const float* P4    = (const float*)d_in[2];
    const float* P5    = (const float*)d_in[3];
    const float* rois  = (const float*)d_in[4];
    const int*   label = (const int*)  d_in[5];
    const float* loc   = (const float*)d_in[6];
    const float* W1    = (const float*)d_in[7];
    const float* b1    = (const float*)d_in[8];
    const float* W2    = (const float*)d_in[9];
    const float* b2    = (const float*)d_in[10];
    const float* Wcls  = (const float*)d_in[11];
    const float* bcls  = (const float*)d_in[12];
    const float* Wloc  = (const float*)d_in[13];
    const float* bloc  = (const float*)d_in[14];
    float* out = (float*)d_out;

    __half *featT, *xb, *w1t, *w2t, *wht, *h1, *h2;
    float *bh, *head, *partb;
    cudaGetSymbolAddress((void**)&featT, g_featT);
    cudaGetSymbolAddress((void**)&xb,    g_x);
    cudaGetSymbolAddress((void**)&w1t,   g_W1T);
    cudaGetSymbolAddress((void**)&w2t,   g_W2T);
    cudaGetSymbolAddress((void**)&wht,   g_WhT);
    cudaGetSymbolAddress((void**)&bh,    g_bh);
    cudaGetSymbolAddress((void**)&h1,    g_h1);
    cudaGetSymbolAddress((void**)&h2,    g_h2);
    cudaGetSymbolAddress((void**)&head,  g_head);
    cudaGetSymbolAddress((void**)&partb, g_part);

    // weight prep (v3 tile engines)
    w1t_v3<<<dim3(KDIM / 256, HID / 32), 256>>>(W1, w1t);
    w2t_v3<<<dim3(HID / 256, HID / 32), 256>>>(W2, w2t);
    whead_kernel<<<dim3(HID / 256, NHEADP), 256>>>(Wcls, Wloc, bcls, bloc, wht, bh);

    // feature transpose (v3)
    transpose_all_v3<<<2125, 256>>>(P2, P3, P4, P5, featT);

    // RoIAlign (v2)
    pool_v2<<<NROI, 256>>>(rois, (const __half2*)featT, (__half2*)xb);

    // FC1 (split-K = 4)
    gemm_hmma<<<dim3(HID / 64, NROI / 128, 4), 256>>>(xb, w1t, partb, HID, KDIM, KDIM / 4);
    combine_kernel<4, true, true><<<(NROI * HID + 255) / 256, 256>>>(partb, b1, h1, HID);

    // FC2 (split-K = 2)
    gemm_hmma<<<dim3(HID / 64, NROI / 128, 2), 256>>>(h1, w2t, partb, HID, HID, HID / 2);
    combine_kernel<2, true, true><<<(NROI * HID + 255) / 256, 256>>>(partb, b2, h2, HID);

    // heads (split-K = 2)
    gemm_hmma<<<dim3(NHEADP / 64, NROI / 128, 2), 256>>>(h2, wht, partb, NHEADP, HID, HID / 2);
    combine_kernel<2, false, false><<<(NROI * NHEADP + 255) / 256, 256>>>(partb, bh, head, NHEADP);

    loss_kernel<<<1, 512>>>(head, label, loc, out);
}

// round 8
// speedup vs baseline: 1.8527x; 1.0340x over previous
#include <cuda_runtime.h>
#include <cuda_fp16.h>
#include <math.h>
#include <stdint.h>

#define NROI 512
#define NPOS 128
#define NCLS 81
#define KDIM 12544   // 256*49
#define HID  1024
#define NCLSP 128    // padded cls head
#define NWROWS 512   // 128 cls rows + 384 loc rows in WhT

// ---------------- scratch ----------------
__device__ __align__(256) __half g_featT[17408000];
__device__ __align__(256) __half g_x[NROI * KDIM];
__device__ __align__(256) __half g_W1T[HID * KDIM];
__device__ __align__(256) __half g_W2T[HID * HID];
__device__ __align__(256) __half g_WhT[NWROWS * HID];
__device__ float g_bh[NWROWS];
__device__ __align__(256) __half g_h1[NROI * HID];
__device__ __align__(256) __half g_h2[NROI * HID];
__device__ float g_head[NROI * NCLSP];
__device__ float g_locp4[NROI * 4];
__device__ float g_part[4 * NROI * HID];

// ---------------- helpers ----------------
__device__ __forceinline__ uint32_t smem_u32(const void* p) {
    uint32_t a;
    asm("{ .reg .u64 t; cvta.to.shared.u64 t, %1; cvt.u32.u64 %0, t; }" : "=r"(a) : "l"(p));
    return a;
}
#define CP_ASYNC16(dst, src) asm volatile("cp.async.cg.shared.global [%0], [%1], 16;" :: "r"(dst), "l"(src))
#define CP_COMMIT() asm volatile("cp.async.commit_group;" ::: "memory")
#define CP_WAIT(n)  asm volatile("cp.async.wait_group %0;" :: "n"(n) : "memory")

#define LDSM_X4(r0, r1, r2, r3, a) \
    asm volatile("ldmatrix.sync.aligned.m8n8.x4.shared.b16 {%0,%1,%2,%3}, [%4];" \
        : "=r"(r0), "=r"(r1), "=r"(r2), "=r"(r3) : "r"(a))

#define MMA16816(d, a, b0, b1) \
    asm volatile("mma.sync.aligned.m16n8k16.row.col.f32.f16.f16.f32 " \
        "{%0,%1,%2,%3}, {%4,%5,%6,%7}, {%8,%9}, {%0,%1,%2,%3};" \
        : "+f"((d)[0]), "+f"((d)[1]), "+f"((d)[2]), "+f"((d)[3]) \
        : "r"((a)[0]), "r"((a)[1]), "r"((a)[2]), "r"((a)[3]), "r"(b0), "r"(b1))

// ============ merged prep: feature transpose + W1T + W2T + WhT/bh ============
// blocks: [0,2125) transpose, [2125,3693) w1t, [3693,3821) w2t, [3821,5869) whead
__global__ void __launch_bounds__(256) prep_kernel(
        const float* __restrict__ P2, const float* __restrict__ P3,
        const float* __restrict__ P4, const float* __restrict__ P5,
        const float* __restrict__ W1, const float* __restrict__ W2,
        const float* __restrict__ Wcls, const float* __restrict__ Wloc,
        const float* __restrict__ bcls, const float* __restrict__ bloc,
        __half* __restrict__ featT, __half* __restrict__ W1T,
        __half* __restrict__ W2T, __half* __restrict__ WhT, float* __restrict__ bh) {
    __shared__ __align__(16) __half2 s2[32][132];
    int b = blockIdx.x;
    int w = threadIdx.x >> 5, l = threadIdx.x & 31;

    if (b < 2125) {
        // ---- feature transpose: tile 32 pos x 256 ch ----
        int lv, pt;
        if (b < 1600)      { lv = 0; pt = b; }
        else if (b < 2000) { lv = 1; pt = b - 1600; }
        else if (b < 2100) { lv = 2; pt = b - 2000; }
        else               { lv = 3; pt = b - 2100; }
        const int HWs[4]   = {51200, 12800, 3200, 800};
        const int bases[4] = {0, 13107200, 16384000, 17203200};
        const float* srcs[4] = {P2, P3, P4, P5};
        int HW = HWs[lv];
        const float* src = srcs[lv];
        __half* dst = featT + bases[lv];
        int p0 = pt * 32;
        #pragma unroll
        for (int m = 0; m < 4; m++) {
            int cp0 = w * 16 + m * 4;
            __half2 v[4];
            #pragma unroll
            for (int q = 0; q < 4; q++) {
                int c = 2 * (cp0 + q);
                float a = src[(size_t)c * HW + p0 + l];
                float bb = src[(size_t)(c + 1) * HW + p0 + l];
                v[q] = __floats2half2_rn(a, bb);
            }
            *(uint4*)&s2[l][cp0] = *(uint4*)v;
        }
        __syncthreads();
        #pragma unroll
        for (int j = 0; j < 4; j++) {
            int idx = j * 256 + threadIdx.x;
            int pos = idx >> 5, seg = idx & 31;
            uint4 val = *(uint4*)&s2[pos][seg * 4];
            *(uint4*)(dst + (size_t)(p0 + pos) * 256 + seg * 8) = val;
        }
    } else if (b < 3693) {
        // ---- W1T (permuted): tile 32 j x 256 k ----
        int lb = b - 2125;
        int k0 = (lb % 49) * 256;
        int j0 = (lb / 49) * 32;
        #pragma unroll
        for (int m = 0; m < 4; m++) {
            int cp0 = w * 16 + m * 4;
            __half2 v[4];
            #pragma unroll
            for (int q = 0; q < 4; q++) {
                int ka = k0 + 2 * (cp0 + q), kb = ka + 1;
                int ra = (ka & 255) * 49 + (ka >> 8);
                int rb = (kb & 255) * 49 + (kb >> 8);
                float a = W1[(size_t)ra * HID + j0 + l];
                float bb = W1[(size_t)rb * HID + j0 + l];
                v[q] = __floats2half2_rn(a, bb);
            }
            *(uint4*)&s2[l][cp0] = *(uint4*)v;
        }
        __syncthreads();
        #pragma unroll
        for (int j = 0; j < 4; j++) {
            int idx = j * 256 + threadIdx.x;
            int jr = idx >> 5, seg = idx & 31;
            uint4 val = *(uint4*)&s2[jr][seg * 4];
            *(uint4*)(W1T + (size_t)(j0 + jr) * KDIM + k0 + seg * 8) = val;
        }
    } else if (b < 3821) {
        // ---- W2T: tile 32 j x 256 k ----
        int lb = b - 3693;
        int k0 = (lb & 3) * 256;
        int j0 = (lb >> 2) * 32;
        #pragma unroll
        for (int m = 0; m < 4; m++) {
            int cp0 = w * 16 + m * 4;
            __half2 v[4];
            #pragma unroll
            for (int q = 0; q < 4; q++) {
                int ka = k0 + 2 * (cp0 + q);
                float a = W2[(size_t)ka * HID + j0 + l];
                float bb = W2[(size_t)(ka + 1) * HID + j0 + l];
                v[q] = __floats2half2_rn(a, bb);
            }
            *(uint4*)&s2[l][cp0] = *(uint4*)v;
        }
        __syncthreads();
        #pragma unroll
        for (int j = 0; j < 4; j++) {
            int idx = j * 256 + threadIdx.x;
            int jr = idx >> 5, seg = idx & 31;
            uint4 val = *(uint4*)&s2[jr][seg * 4];
            *(uint4*)(W2T + (size_t)(j0 + jr) * HID + k0 + seg * 8) = val;
        }
    } else {
        // ---- WhT row j (cls rows 0..127, loc rows 128..511) + bias ----
        int lb = b - 3821;
        int j = lb >> 2;
        int k = (lb & 3) * 256 + threadIdx.x;
        float v = 0.0f;
        if (j < NCLSP) {
            if (j < NCLS) v = Wcls[(size_t)k * NCLS + j];
        } else {
            int jj = j - NCLSP;
            if (jj < NCLS * 4) v = Wloc[(size_t)k * (NCLS * 4) + jj];
        }
        WhT[(size_t)j * HID + k] = __float2half(v);
        if ((lb & 3) == 0 && threadIdx.x == 0) {
            float bv = 0.0f;
            if (j < NCLSP) { if (j < NCLS) bv = bcls[j]; }
            else { int jj = j - NCLSP; if (jj < NCLS * 4) bv = bloc[jj]; }
            bh[j] = bv;
        }
    }
}

// ============ RoIAlign: one block per ROI, half2 channels ============
__global__ void __launch_bounds__(256) pool_v2(const float* __restrict__ rois,
                                               const __half2* __restrict__ featT2,
                                               __half2* __restrict__ xout2) {
    int n = blockIdx.x;
    int cidx = threadIdx.x & 127;
    int h = threadIdx.x >> 7;

    float rx1 = rois[n * 4 + 0], ry1 = rois[n * 4 + 1];
    float rx2 = rois[n * 4 + 2], ry2 = rois[n * 4 + 3];
    float area = (rx2 - rx1 + 1.0f) * (ry2 - ry1 + 1.0f);
    float lf = floorf(4.0f + log2f(sqrtf(area) / 224.0f));
    lf = fminf(fmaxf(lf, 2.0f), 5.0f);
    int lv = (int)lf - 2;

    const int   Hs[4]     = {200, 100, 50, 25};
    const int   Ws[4]     = {256, 128, 64, 32};
    const int   bases2[4] = {0, 6553600, 8192000, 8601600};
    const float scl[4]    = {0.25f, 0.125f, 0.0625f, 0.03125f};

    int H = Hs[lv], W = Ws[lv];
    const __half2* ft = featT2 + bases2[lv];
    float scale = scl[lv];

    float x1 = rx1 * scale, y1 = ry1 * scale;
    float x2 = rx2 * scale, y2 = ry2 * scale;
    float bw = fmaxf(x2 - x1, 1.0f) / 7.0f;
    float bh = fmaxf(y2 - y1, 1.0f) / 7.0f;

    for (int bin = h; bin < 49; bin += 2) {
        int oy = bin / 7, ox = bin % 7;
        float2 acc = make_float2(0.0f, 0.0f);
        #pragma unroll
        for (int sy = 0; sy < 2; sy++) {
            #pragma unroll
            for (int sx = 0; sx < 2; sx++) {
                float px = x1 + ((float)ox + ((float)sx + 0.5f) * 0.5f) * bw;
                float py = y1 + ((float)oy + ((float)sy + 0.5f) * 0.5f) * bh;
                bool valid = (px > -1.0f) && (px < (float)W) && (py > -1.0f) && (py < (float)H);
                if (!valid) continue;
                float xx = fminf(fmaxf(px, 0.0f), (float)(W - 1));
                float yy = fminf(fmaxf(py, 0.0f), (float)(H - 1));
                float x0f = floorf(xx), y0f = floorf(yy);
                float lx = xx - x0f, ly = yy - y0f;
                int x0 = (int)x0f, y0 = (int)y0f;
                int x1i = min(x0 + 1, W - 1), y1i = min(y0 + 1, H - 1);
                const __half2* r0 = ft + (size_t)(y0  * W) * 128;
                const __half2* r1 = ft + (size_t)(y1i * W) * 128;
                float w00 = (1.0f - ly) * (1.0f - lx);
                float w01 = (1.0f - ly) * lx;
                float w10 = ly * (1.0f - lx);
                float w11 = ly * lx;
                float2 v00 = __half22float2(r0[x0  * 128 + cidx]);
                float2 v01 = __half22float2(r0[x1i * 128 + cidx]);
                float2 v10 = __half22float2(r1[x0  * 128 + cidx]);
                float2 v11 = __half22float2(r1[x1i * 128 + cidx]);
                acc.x += w00 * v00.x + w01 * v01.x + w10 * v10.x + w11 * v11.x;
                acc.y += w00 * v00.y + w01 * v01.y + w10 * v10.y + w11 * v11.y;
            }
        }
        xout2[(size_t)n * (KDIM / 2) + bin * 128 + cidx] =
            __floats2half2_rn(acc.x * 0.25f, acc.y * 0.25f);
    }
}

// ---------------- HMMA GEMM, 4-stage pipeline: part[z][M][N] = A @ Bt^T ----------------
// BM=128, BN=64, BK=32. 256 threads. Buffers: A 4x4096 halves, B 4x2048 halves.
__global__ void __launch_bounds__(256) gemm_hmma(const __half* __restrict__ A,
                                                 const __half* __restrict__ Bt,
                                                 float* __restrict__ part,
                                                 int N, int Krow, int ksplit) {
    __shared__ __align__(128) __half As[4][128 * 32];
    __shared__ __align__(128) __half Bs[4][64 * 32];

    int tid = threadIdx.x, wid = tid >> 5, lane = tid & 31;
    int m0 = blockIdx.y * 128, n0 = blockIdx.x * 64;
    int z = blockIdx.z;
    int kb0 = z * ksplit;
    int wm = (wid & 3) * 32;
    int wn = (wid >> 2) * 32;

    uint32_t sA = smem_u32(As), sB = smem_u32(Bs);
    int nch = ksplit >> 5;

    int ldr = tid >> 2, ldc = tid & 3;
    int swA0 = (ldc ^ ((ldr >> 1) & 3));
    int rowA1 = ldr + 64;
    int swA1 = (ldc ^ ((rowA1 >> 1) & 3));
    uint32_t stA0 = sA + (ldr * 32 + swA0 * 8) * 2;
    uint32_t stA1 = sA + (rowA1 * 32 + swA1 * 8) * 2;
    uint32_t stB0 = sB + (ldr * 32 + swA0 * 8) * 2;
    const char* gA0 = (const char*)(A + (size_t)(m0 + ldr) * Krow + kb0) + ldc * 16;
    const char* gA1 = (const char*)(A + (size_t)(m0 + rowA1) * Krow + kb0) + ldc * 16;
    const char* gB0 = (const char*)(Bt + (size_t)(n0 + ldr) * Krow + kb0) + ldc * 16;

    // prologue: stages 0..2
    #pragma unroll
    for (int p = 0; p < 3; p++) {
        int koff = p << 6;   // 32 halves * 2B
        CP_ASYNC16(stA0 + p * 8192, gA0 + koff);
        CP_ASYNC16(stA1 + p * 8192, gA1 + koff);
        CP_ASYNC16(stB0 + p * 4096, gB0 + koff);
        CP_COMMIT();
    }

    float acc[2][4][4];
    #pragma unroll
    for (int mi = 0; mi < 2; mi++)
        #pragma unroll
        for (int ni = 0; ni < 4; ni++)
            #pragma unroll
            for (int j = 0; j < 4; j++) acc[mi][ni][j] = 0.0f;

    for (int k = 0; k < nch; k++) {
        if (k + 3 < nch) { CP_WAIT(2); } else { CP_WAIT(0); }
        __syncthreads();
        if (k + 3 < nch) {
            int p = (k + 3) & 3;
            int koff = (k + 3) << 6;
            CP_ASYNC16(stA0 + p * 8192, gA0 + koff);
            CP_ASYNC16(stA1 + p * 8192, gA1 + koff);
            CP_ASYNC16(stB0 + p * 4096, gB0 + koff);
            CP_COMMIT();
        }
        int buf = k & 3;

        uint32_t bf[4][4];
        #pragma unroll
        for (int ni = 0; ni < 4; ni++) {
            int row = wn + ni * 8 + (lane & 7);
            int ch = lane >> 3;
            int sw = ch ^ ((row >> 1) & 3);
            uint32_t a = sB + (buf * 2048 + row * 32 + sw * 8) * 2;
            LDSM_X4(bf[ni][0], bf[ni][1], bf[ni][2], bf[ni][3], a);
        }
        #pragma unroll
        for (int s = 0; s < 2; s++) {
            uint32_t af[2][4];
            #pragma unroll
            for (int mi = 0; mi < 2; mi++) {
                int row = wm + mi * 16 + (lane & 15);
                int ch = 2 * s + (lane >> 4);
                int sw = ch ^ ((row >> 1) & 3);
                uint32_t a = sA + (buf * 4096 + row * 32 + sw * 8) * 2;
                LDSM_X4(af[mi][0], af[mi][1], af[mi][2], af[mi][3], a);
            }
            #pragma unroll
            for (int mi = 0; mi < 2; mi++)
                #pragma unroll
                for (int ni = 0; ni < 4; ni++)
                    MMA16816(acc[mi][ni], af[mi], bf[ni][2 * s], bf[ni][2 * s + 1]);
        }
    }

    float* out = part + (size_t)z * NROI * N;
    #pragma unroll
    for (int mi = 0; mi < 2; mi++) {
        #pragma unroll
        for (int ni = 0; ni < 4; ni++) {
            int m = m0 + wm + mi * 16 + (lane >> 2);
            int n = n0 + wn + ni * 8 + (lane & 3) * 2;
            out[(size_t)m * N + n]           = acc[mi][ni][0];
            out[(size_t)m * N + n + 1]       = acc[mi][ni][1];
            out[(size_t)(m + 8) * N + n]     = acc[mi][ni][2];
            out[(size_t)(m + 8) * N + n + 1] = acc[mi][ni][3];
        }
    }
}

// ---------------- combine ----------------
template <int SPLIT, bool RELU, bool HOUT>
__global__ void combine_kernel(const float* __restrict__ part, const float* __restrict__ bias,
                               void* __restrict__ out, int N) {
    int idx = blockIdx.x * 256 + threadIdx.x;
    int MN = NROI * N;
    if (idx >= MN) return;
    int n = idx % N;
    float v = bias[n];
    #pragma unroll
    for (int z = 0; z < SPLIT; z++) v += part[(size_t)z * MN + idx];
    if (RELU) v = fmaxf(v, 0.0f);
    if (HOUT) ((__half*)out)[idx] = __float2half(v);
    else      ((float*)out)[idx] = v;
}

// ---------------- loc select: locp4[n][j] = h2[n,:] . WhT[128+lab*4+j,:] + bh ----------------
__global__ void __launch_bounds__(128) loc_select_kernel(const __half* __restrict__ h2,
                                                         const __half* __restrict__ WhT,
                                                         const float* __restrict__ bh,
                                                         const int* __restrict__ label,
                                                         float* __restrict__ locp4) {
    int n = blockIdx.x;
    int j = threadIdx.x >> 5, lane = threadIdx.x & 31;
    int row = NCLSP + label[n] * 4 + j;
    const __half2* hv = (const __half2*)(h2 + (size_t)n * HID);
    const __half2* wv = (const __half2*)(WhT + (size_t)row * HID);
    float acc = 0.0f;
    #pragma unroll
    for (int i = 0; i < 16; i++) {
        float2 a = __half22float2(hv[lane + i * 32]);
        float2 b = __half22float2(wv[lane + i * 32]);
        acc += a.x * b.x + a.y * b.y;
    }
    #pragma unroll
    for (int off = 16; off > 0; off >>= 1)
        acc += __shfl_down_sync(0xFFFFFFFF, acc, off);
    if (lane == 0) locp4[n * 4 + j] = acc + bh[row];
}

// ---------------- loss ----------------
__global__ void loss_kernel(const float* __restrict__ head, const float* __restrict__ locp4,
                            const int* __restrict__ label, const float* __restrict__ loc,
                            float* __restrict__ out) {
    __shared__ float red[512];
    int n = threadIdx.x;
    const float* lg = head + (size_t)n * NCLSP;

    float mx = -1e30f;
    for (int j = 0; j < NCLS; j++) mx = fmaxf(mx, lg[j]);
    float s = 0.0f;
    for (int j = 0; j < NCLS; j++) s += expf(lg[j] - mx);
    int lab = label[n];
    float logp = lg[lab] - mx - logf(s);
    float contrib = -logp * (1.0f / (float)NROI);

    if (n < NPOS) {
        #pragma unroll
        for (int j = 0; j < 4; j++) {
            float d = fabsf(locp4[n * 4 + j] - loc[n * 4 + j]);
            float sl1 = (d < 1.0f) ? 0.5f * d * d : d - 0.5f;
            contrib += sl1 * (1.0f / (float)NROI);
        }
    }
    red[n] = contrib;
    __syncthreads();
    for (int stride = 256; stride > 0; stride >>= 1) {
        if (n < stride) red[n] += red[n + stride];
        __syncthreads();
    }
    if (n == 0) out[0] = red[0];
}

// ---------------- launch ----------------
extern "C" void kernel_launch(void* const* d_in, const int* in_sizes, int n_in,
                              void* d_out, int out_size) {
    const float* P2    = (const float*)d_in[0];
    const float* P3    = (const float*)d_in[1];
    const float* P4    = (const float*)d_in[2];
    const float* P5    = (const float*)d_in[3];
    const float* rois  = (const float*)d_in[4];
    const int*   label = (const int*)  d_in[5];
    const float* loc   = (const float*)d_in[6];
    const float* W1    = (const float*)d_in[7];
    const float* b1    = (const float*)d_in[8];
    const float* W2    = (const float*)d_in[9];
    const float* b2    = (const float*)d_in[10];
    const float* Wcls  = (const float*)d_in[11];
    const float* bcls  = (const float*)d_in[12];
    const float* Wloc  = (const float*)d_in[13];
    const float* bloc  = (const float*)d_in[14];
    float* out = (float*)d_out;

    __half *featT, *xb, *w1t, *w2t, *wht, *h1, *h2;
    float *bh, *head, *locp4, *partb;
    cudaGetSymbolAddress((void**)&featT, g_featT);
    cudaGetSymbolAddress((void**)&xb,    g_x);
    cudaGetSymbolAddress((void**)&w1t,   g_W1T);
    cudaGetSymbolAddress((void**)&w2t,   g_W2T);
    cudaGetSymbolAddress((void**)&wht,   g_WhT);
    cudaGetSymbolAddress((void**)&bh,    g_bh);
    cudaGetSymbolAddress((void**)&h1,    g_h1);
    cudaGetSymbolAddress((void**)&h2,    g_h2);
    cudaGetSymbolAddress((void**)&head,  g_head);
    cudaGetSymbolAddress((void**)&locp4, g_locp4);
    cudaGetSymbolAddress((void**)&partb, g_part);

    // merged prep (1 launch)
    prep_kernel<<<5869, 256>>>(P2, P3, P4, P5, W1, W2, Wcls, Wloc, bcls, bloc,
                               featT, w1t, w2t, wht, bh);

    // RoIAlign
    pool_v2<<<NROI, 256>>>(rois, (const __half2*)featT, (__half2*)xb);

    // FC1 (split-K = 4)
    gemm_hmma<<<dim3(HID / 64, NROI / 128, 4), 256>>>(xb, w1t, partb, HID, KDIM, KDIM / 4);
    combine_kernel<4, true, true><<<(NROI * HID + 255) / 256, 256>>>(partb, b1, h1, HID);

    // FC2 (split-K = 2)
    gemm_hmma<<<dim3(HID / 64, NROI / 128, 2), 256>>>(h1, w2t, partb, HID, HID, HID / 2);
    combine_kernel<2, true, true><<<(NROI * HID + 255) / 256, 256>>>(partb, b2, h2, HID);

    // cls head (split-K = 2, N=128)
    gemm_hmma<<<dim3(NCLSP / 64, NROI / 128, 2), 256>>>(h2, wht, partb, NCLSP, HID, HID / 2);
    combine_kernel<2, false, false><<<(NROI * NCLSP + 255) / 256, 256>>>(partb, bh, head, NCLSP);

    // loc head (selected rows only)
    loc_select_kernel<<<NROI, 128>>>(h2, wht, bh, label, locp4);

    loss_kernel<<<1, 512>>>(head, locp4, label, loc, out);
}